// round 1
// baseline (speedup 1.0000x reference)
#include <cuda_runtime.h>
#include <math.h>

#define TSEQ 2048
#define NE   1024
#define NH   16
#define DKH  64
#define NB   2
#define MTOT (NB*TSEQ)   // 4096

// Scratch (allocation-free): Q, K, V projections and attention output Y, all [B,T,E] fp32.
__device__ float g_Q[MTOT*NE];
__device__ float g_K[MTOT*NE];
__device__ float g_V[MTOT*NE];
__device__ float g_Y[MTOT*NE];

// ---------------------------------------------------------------------------
// C = A[M,K] * W[N,K]^T + bias   (M=4096, N=1024, K=1024), 128x128x16 tiles,
// 256 threads, 8x8 per-thread micro-tile. blockIdx.z selects (W, bias, C).
// ---------------------------------------------------------------------------
__global__ __launch_bounds__(256, 2)
void gemm_nt_bias(const float* __restrict__ A,
                  const float* __restrict__ W0, const float* __restrict__ W1, const float* __restrict__ W2,
                  const float* __restrict__ b0, const float* __restrict__ b1, const float* __restrict__ b2,
                  float* __restrict__ C0, float* __restrict__ C1, float* __restrict__ C2)
{
    const float* W; const float* bias; float* C;
    if (blockIdx.z == 0)      { W = W0; bias = b0; C = C0; }
    else if (blockIdx.z == 1) { W = W1; bias = b1; C = C1; }
    else                      { W = W2; bias = b2; C = C2; }

    __shared__ float As[16][132];   // [k][m], padded
    __shared__ float Bs[16][132];   // [k][n], padded

    const int tid = threadIdx.x;
    const int ty  = tid >> 4;      // 0..15 -> rows ty*8..+7
    const int tx  = tid & 15;      // 0..15 -> cols tx*8..+7
    const int mbase = blockIdx.y * 128;
    const int nbase = blockIdx.x * 128;
    const int lm  = tid >> 2;      // 0..63
    const int lk4 = (tid & 3) * 4; // 0,4,8,12

    float acc[8][8];
#pragma unroll
    for (int i = 0; i < 8; i++)
#pragma unroll
        for (int j = 0; j < 8; j++) acc[i][j] = 0.f;

    for (int kt = 0; kt < NE; kt += 16) {
#pragma unroll
        for (int hh = 0; hh < 2; hh++) {
            int m = lm + hh * 64;
            float4 va = *(const float4*)(A + (size_t)(mbase + m) * NE + kt + lk4);
            As[lk4+0][m] = va.x; As[lk4+1][m] = va.y; As[lk4+2][m] = va.z; As[lk4+3][m] = va.w;
            float4 vb = *(const float4*)(W + (size_t)(nbase + m) * NE + kt + lk4);
            Bs[lk4+0][m] = vb.x; Bs[lk4+1][m] = vb.y; Bs[lk4+2][m] = vb.z; Bs[lk4+3][m] = vb.w;
        }
        __syncthreads();
#pragma unroll
        for (int k = 0; k < 16; k++) {
            float a[8], b[8];
            *(float4*)(a)     = *(const float4*)&As[k][ty*8];
            *(float4*)(a + 4) = *(const float4*)&As[k][ty*8 + 4];
            *(float4*)(b)     = *(const float4*)&Bs[k][tx*8];
            *(float4*)(b + 4) = *(const float4*)&Bs[k][tx*8 + 4];
#pragma unroll
            for (int i = 0; i < 8; i++)
#pragma unroll
                for (int j = 0; j < 8; j++)
                    acc[i][j] += a[i] * b[j];
        }
        __syncthreads();
    }

    float4 bv1 = *(const float4*)(bias + nbase + tx*8);
    float4 bv2 = *(const float4*)(bias + nbase + tx*8 + 4);
#pragma unroll
    for (int i = 0; i < 8; i++) {
        size_t row = (size_t)(mbase + ty*8 + i);
        float4 o1 = make_float4(acc[i][0] + bv1.x, acc[i][1] + bv1.y,
                                acc[i][2] + bv1.z, acc[i][3] + bv1.w);
        float4 o2 = make_float4(acc[i][4] + bv2.x, acc[i][5] + bv2.y,
                                acc[i][6] + bv2.z, acc[i][7] + bv2.w);
        *(float4*)(C + row * NE + nbase + tx*8)     = o1;
        *(float4*)(C + row * NE + nbase + tx*8 + 4) = o2;
    }
}

// ---------------------------------------------------------------------------
// Flash attention, fp32. One block per (q-tile of 64 rows, b*h).
// 256 threads: ty=tid/16 (4 rows each), tx=tid%16 (4 cols each).
// Smem tiles 64x64, XOR-swizzled at float4 granularity: blk' = blk ^ (row>>2).
// Pt (softmax probs, transposed) reuses the Ks buffer -> 48KB static smem.
// ---------------------------------------------------------------------------
__global__ __launch_bounds__(256, 2)
void attn_kernel(const float* __restrict__ Q, const float* __restrict__ K,
                 const float* __restrict__ V, float* __restrict__ Y)
{
    __shared__ float Qs[64][64];
    __shared__ float Ks[64][64];   // K tile, later reused as P^T
    __shared__ float Vs[64][64];

    const int tid = threadIdx.x;
    const int ty  = tid >> 4;   // 0..15
    const int tx  = tid & 15;   // 0..15
    const int qt  = (int)gridDim.x - 1 - (int)blockIdx.x;  // heavy tiles first
    const int bh  = blockIdx.y;
    const int b   = bh >> 4;
    const int h   = bh & 15;
    const size_t base = (size_t)b * TSEQ * NE + (size_t)h * DKH;

    // Load Q tile (pre-scaled by 1/sqrt(64) = 0.125), swizzled.
#pragma unroll
    for (int it = 0; it < 4; it++) {
        int idx = tid + it * 256;
        int r   = idx >> 4;
        int blk = idx & 15;
        float4 v = *(const float4*)(Q + base + (size_t)(qt*64 + r) * NE + blk*4);
        v.x *= 0.125f; v.y *= 0.125f; v.z *= 0.125f; v.w *= 0.125f;
        ((float4*)&Qs[r][0])[blk ^ (r >> 2)] = v;
    }

    float m_r[4], l_r[4], o[4][4];
#pragma unroll
    for (int i = 0; i < 4; i++) {
        m_r[i] = -1e30f; l_r[i] = 0.f;
#pragma unroll
        for (int j = 0; j < 4; j++) o[i][j] = 0.f;
    }
    __syncthreads();

    for (int kt = 0; kt <= qt; kt++) {
        // Load K and V tiles (swizzled).
#pragma unroll
        for (int it = 0; it < 4; it++) {
            int idx = tid + it * 256;
            int r   = idx >> 4;
            int blk = idx & 15;
            int sw  = blk ^ (r >> 2);
            ((float4*)&Ks[r][0])[sw] = *(const float4*)(K + base + (size_t)(kt*64 + r) * NE + blk*4);
            ((float4*)&Vs[r][0])[sw] = *(const float4*)(V + base + (size_t)(kt*64 + r) * NE + blk*4);
        }
        __syncthreads();

        // S[4x4] = Q-rows (ty*4+i) . K-rows (tx*4+j)
        float s[4][4];
#pragma unroll
        for (int i = 0; i < 4; i++)
#pragma unroll
            for (int j = 0; j < 4; j++) s[i][j] = 0.f;

#pragma unroll
        for (int d4 = 0; d4 < 16; d4++) {
            float4 a[4];
#pragma unroll
            for (int i = 0; i < 4; i++)
                a[i] = ((const float4*)&Qs[ty*4 + i][0])[d4 ^ ty];
#pragma unroll
            for (int j = 0; j < 4; j++) {
                float4 bb = ((const float4*)&Ks[tx*4 + j][0])[d4 ^ tx];
#pragma unroll
                for (int i = 0; i < 4; i++)
                    s[i][j] += a[i].x*bb.x + a[i].y*bb.y + a[i].z*bb.z + a[i].w*bb.w;
            }
        }

        // Causal mask on the diagonal tile.
        if (kt == qt) {
#pragma unroll
            for (int i = 0; i < 4; i++)
#pragma unroll
                for (int j = 0; j < 4; j++)
                    if (tx*4 + j > ty*4 + i) s[i][j] = -1e30f;
        }

        // Online softmax; row stats reduced over the 16 tx-lanes (same half-warp).
#pragma unroll
        for (int i = 0; i < 4; i++) {
            float mx = fmaxf(fmaxf(s[i][0], s[i][1]), fmaxf(s[i][2], s[i][3]));
#pragma unroll
            for (int off = 1; off < 16; off <<= 1)
                mx = fmaxf(mx, __shfl_xor_sync(0xffffffffu, mx, off));
            float mnew = fmaxf(m_r[i], mx);
            float corr = __expf(m_r[i] - mnew);
            float rsum = 0.f;
#pragma unroll
            for (int j = 0; j < 4; j++) { s[i][j] = __expf(s[i][j] - mnew); rsum += s[i][j]; }
#pragma unroll
            for (int off = 1; off < 16; off <<= 1)
                rsum += __shfl_xor_sync(0xffffffffu, rsum, off);
            l_r[i] = l_r[i] * corr + rsum;
            m_r[i] = mnew;
#pragma unroll
            for (int j = 0; j < 4; j++) o[i][j] *= corr;
        }

        __syncthreads();               // everyone done reading Ks
        // Write P^T into Ks buffer: Pt[c][r], swizzled block = ty ^ (c>>2) = ty ^ tx.
#pragma unroll
        for (int j = 0; j < 4; j++) {
            int c = tx*4 + j;
#pragma unroll
            for (int i = 0; i < 4; i++)
                Ks[c][((ty ^ tx) << 2) + i] = s[i][j];
        }
        __syncthreads();

        // O[4x4] += P^T-cols . V-rows
#pragma unroll 8
        for (int c = 0; c < 64; c++) {
            int sw = c >> 2;
            float4 a  = ((const float4*)&Ks[c][0])[ty ^ sw];  // P[ty*4..+3][c]
            float4 bb = ((const float4*)&Vs[c][0])[tx ^ sw];  // V[c][tx*4..+3]
            o[0][0] += a.x*bb.x; o[0][1] += a.x*bb.y; o[0][2] += a.x*bb.z; o[0][3] += a.x*bb.w;
            o[1][0] += a.y*bb.x; o[1][1] += a.y*bb.y; o[1][2] += a.y*bb.z; o[1][3] += a.y*bb.w;
            o[2][0] += a.z*bb.x; o[2][1] += a.z*bb.y; o[2][2] += a.z*bb.z; o[2][3] += a.z*bb.w;
            o[3][0] += a.w*bb.x; o[3][1] += a.w*bb.y; o[3][2] += a.w*bb.z; o[3][3] += a.w*bb.w;
        }
        __syncthreads();               // protect Ks/Vs for next iteration
    }

    // Normalize and write out.
#pragma unroll
    for (int i = 0; i < 4; i++) {
        float inv = 1.f / l_r[i];
        float4 out = make_float4(o[i][0]*inv, o[i][1]*inv, o[i][2]*inv, o[i][3]*inv);
        *(float4*)(Y + base + (size_t)(qt*64 + ty*4 + i) * NE + tx*4) = out;
    }
}

// ---------------------------------------------------------------------------
extern "C" void kernel_launch(void* const* d_in, const int* in_sizes, int n_in,
                              void* d_out, int out_size)
{
    const float* x  = (const float*)d_in[0];
    const float* Wq = (const float*)d_in[1];
    const float* bq = (const float*)d_in[2];
    const float* Wk = (const float*)d_in[3];
    const float* bk = (const float*)d_in[4];
    const float* Wv = (const float*)d_in[5];
    const float* bv = (const float*)d_in[6];
    const float* Wo = (const float*)d_in[7];
    const float* bo = (const float*)d_in[8];
    float* out = (float*)d_out;

    float *Qp, *Kp, *Vp, *Yp;
    cudaGetSymbolAddress((void**)&Qp, g_Q);
    cudaGetSymbolAddress((void**)&Kp, g_K);
    cudaGetSymbolAddress((void**)&Vp, g_V);
    cudaGetSymbolAddress((void**)&Yp, g_Y);

    dim3 blk(256);
    // Fused QKV projections: z selects W/bias/output.
    gemm_nt_bias<<<dim3(8, 32, 3), blk>>>(x, Wq, Wk, Wv, bq, bk, bv, Qp, Kp, Vp);
    // Causal flash attention.
    attn_kernel<<<dim3(32, 32), blk>>>(Qp, Kp, Vp, Yp);
    // Output projection.
    gemm_nt_bias<<<dim3(8, 32, 1), blk>>>(Yp, Wo, Wo, Wo, bo, bo, bo, out, out, out);
}

// round 3
// speedup vs baseline: 1.5952x; 1.5952x over previous
#include <cuda_runtime.h>
#include <cuda_bf16.h>
#include <cstdint>
#include <math.h>

#define TSEQ 2048
#define NE   1024
#define NH   16
#define DKH  64
#define NB   2
#define MTOT (NB*TSEQ)   // 4096

// Scratch (allocation-free)
__device__ float g_Q[MTOT*NE];
__device__ float g_K[MTOT*NE];
__device__ float g_V[MTOT*NE];
__device__ float g_Y[MTOT*NE];

// ---------------------------------------------------------------------------
// Baseline-PTX tensor ops (work on plain sm_103 target: no tcgen05 needed)
// ---------------------------------------------------------------------------
static __device__ __forceinline__ uint32_t smem_u32(const void* p) {
    uint32_t a;
    asm("{ .reg .u64 t; cvta.to.shared.u64 t, %1; cvt.u32.u64 %0, t; }" : "=r"(a) : "l"(p));
    return a;
}
static __device__ __forceinline__ void ldsm_x4(uint32_t& r0, uint32_t& r1,
                                               uint32_t& r2, uint32_t& r3, uint32_t a) {
    asm volatile("ldmatrix.sync.aligned.m8n8.x4.shared.b16 {%0,%1,%2,%3}, [%4];"
                 : "=r"(r0), "=r"(r1), "=r"(r2), "=r"(r3) : "r"(a));
}
static __device__ __forceinline__ void mma16816(float* c, const uint32_t* a, const uint32_t* b) {
    asm volatile("mma.sync.aligned.m16n8k16.row.col.f32.bf16.bf16.f32 "
                 "{%0,%1,%2,%3}, {%4,%5,%6,%7}, {%8,%9}, {%0,%1,%2,%3};"
                 : "+f"(c[0]), "+f"(c[1]), "+f"(c[2]), "+f"(c[3])
                 : "r"(a[0]), "r"(a[1]), "r"(a[2]), "r"(a[3]), "r"(b[0]), "r"(b[1]));
}

// Split an fp32 quad into hi/lo bf16 quads and store (8B each).
static __device__ __forceinline__ void split_store(char* hi, char* lo, float4 v) {
    __nv_bfloat16 hx = __float2bfloat16_rn(v.x), hy = __float2bfloat16_rn(v.y);
    __nv_bfloat16 hz = __float2bfloat16_rn(v.z), hw = __float2bfloat16_rn(v.w);
    union { __nv_bfloat162 h[2]; uint2 u; } p;
    p.h[0].x = hx; p.h[0].y = hy; p.h[1].x = hz; p.h[1].y = hw;
    *(uint2*)hi = p.u;
    p.h[0].x = __float2bfloat16_rn(v.x - __bfloat162float(hx));
    p.h[0].y = __float2bfloat16_rn(v.y - __bfloat162float(hy));
    p.h[1].x = __float2bfloat16_rn(v.z - __bfloat162float(hz));
    p.h[1].y = __float2bfloat16_rn(v.w - __bfloat162float(hw));
    *(uint2*)lo = p.u;
}

#define RSTRIDE   80                 // bytes per 32-elem bf16 row (40 elems, conflict-free)
#define TILE_B    (128 * RSTRIDE)    // 10240 bytes per bf16 tile
#define STAGE     (4 * TILE_B)       // Ah | Al | Wh | Wl
#define SMEM_DYN  (2 * STAGE)        // 81920, double-buffered
#define NK        (NE / 32)          // 32 k-chunks

// ---------------------------------------------------------------------------
// C[M,N=1024] = A[M,K=1024] * W[N,K]^T + bias, split-bf16 on mma.sync HMMA.
// 128x128 CTA tile, kchunk 32. blockIdx.z selects (W, bias, C).
// ---------------------------------------------------------------------------
__global__ __launch_bounds__(256)
void gemm_tc(const float* __restrict__ A,
             const float* __restrict__ W0, const float* __restrict__ W1, const float* __restrict__ W2,
             const float* __restrict__ b0, const float* __restrict__ b1, const float* __restrict__ b2,
             float* __restrict__ C0, float* __restrict__ C1, float* __restrict__ C2)
{
    extern __shared__ char smem[];

    const float* W; const float* bias; float* C;
    if (blockIdx.z == 0)      { W = W0; bias = b0; C = C0; }
    else if (blockIdx.z == 1) { W = W1; bias = b1; C = C1; }
    else                      { W = W2; bias = b2; C = C2; }

    const int tid  = threadIdx.x;
    const int wid  = tid >> 5;
    const int lane = tid & 31;
    const int mbase = blockIdx.y * 128;
    const int nbase = blockIdx.x * 128;
    const int warp_m = wid >> 2;        // 0..1 -> 64 rows
    const int warp_n = wid & 3;         // 0..3 -> 32 cols

    // Loader mapping: thread covers rows r0+32i (i=0..3), 4 consecutive floats at c4*4.
    const int r0 = tid >> 3;            // 0..31
    const int c4 = tid & 7;             // 0..7

    // ldmatrix lane offsets
    const int la_row = warp_m * 64 + (lane & 15);
    const int la_k8  = ((lane >> 4) & 1) * 8;
    const int lw_row = warp_n * 32 + (lane & 7) + ((lane >> 4) & 1) * 8;
    const int lw_k8  = ((lane >> 3) & 1) * 8;

    const uint32_t smb = smem_u32(smem);

    float acc[4][4][4];
#pragma unroll
    for (int mi = 0; mi < 4; mi++)
#pragma unroll
        for (int nf = 0; nf < 4; nf++)
#pragma unroll
            for (int q = 0; q < 4; q++) acc[mi][nf][q] = 0.f;

    float4 ra[4], rw[4];

    // prologue: stage 0
#pragma unroll
    for (int i = 0; i < 4; i++) {
        ra[i] = *(const float4*)(A + (size_t)(mbase + r0 + 32*i) * NE + c4 * 4);
        rw[i] = *(const float4*)(W + (size_t)(nbase + r0 + 32*i) * NE + c4 * 4);
    }
#pragma unroll
    for (int i = 0; i < 4; i++) {
        uint32_t off = (uint32_t)(r0 + 32*i) * RSTRIDE + c4 * 8;
        split_store(smem + off,            smem + TILE_B + off,   ra[i]);
        split_store(smem + 2*TILE_B + off, smem + 3*TILE_B + off, rw[i]);
    }
    __syncthreads();

    for (int kt = 0; kt < NK; kt++) {
        const int b = kt & 1;
        if (kt + 1 < NK) {
            const float* Ap = A + (size_t)mbase * NE + (kt + 1) * 32;
            const float* Wp = W + (size_t)nbase * NE + (kt + 1) * 32;
#pragma unroll
            for (int i = 0; i < 4; i++) {
                ra[i] = *(const float4*)(Ap + (size_t)(r0 + 32*i) * NE + c4 * 4);
                rw[i] = *(const float4*)(Wp + (size_t)(r0 + 32*i) * NE + c4 * 4);
            }
        }

        const uint32_t base = smb + b * STAGE;
#pragma unroll
        for (int ks = 0; ks < 2; ks++) {
            uint32_t ah[4][4], al[4][4];
#pragma unroll
            for (int mi = 0; mi < 4; mi++) {
                uint32_t aoff = (uint32_t)(la_row + mi*16) * RSTRIDE + (ks*16 + la_k8) * 2;
                ldsm_x4(ah[mi][0], ah[mi][1], ah[mi][2], ah[mi][3], base + aoff);
                ldsm_x4(al[mi][0], al[mi][1], al[mi][2], al[mi][3], base + TILE_B + aoff);
            }
            uint32_t wh[2][4], wl[2][4];
#pragma unroll
            for (int nj = 0; nj < 2; nj++) {
                uint32_t woff = (uint32_t)(lw_row + nj*16) * RSTRIDE + (ks*16 + lw_k8) * 2;
                ldsm_x4(wh[nj][0], wh[nj][1], wh[nj][2], wh[nj][3], base + 2*TILE_B + woff);
                ldsm_x4(wl[nj][0], wl[nj][1], wl[nj][2], wl[nj][3], base + 3*TILE_B + woff);
            }
#pragma unroll
            for (int mi = 0; mi < 4; mi++)
#pragma unroll
                for (int nf = 0; nf < 4; nf++) {
                    const uint32_t* bh = &wh[nf >> 1][(nf & 1) * 2];
                    const uint32_t* bl = &wl[nf >> 1][(nf & 1) * 2];
                    mma16816(acc[mi][nf], ah[mi], bh);
                    mma16816(acc[mi][nf], ah[mi], bl);
                    mma16816(acc[mi][nf], al[mi], bh);
                }
        }

        if (kt + 1 < NK) {
            char* stg = smem + ((kt + 1) & 1) * STAGE;
#pragma unroll
            for (int i = 0; i < 4; i++) {
                uint32_t off = (uint32_t)(r0 + 32*i) * RSTRIDE + c4 * 8;
                split_store(stg + off,            stg + TILE_B + off,   ra[i]);
                split_store(stg + 2*TILE_B + off, stg + 3*TILE_B + off, rw[i]);
            }
            __syncthreads();
        }
    }

    // epilogue: bias + store
    const int crow  = mbase + warp_m * 64 + (lane >> 2);
    const int ccol0 = nbase + warp_n * 32 + (lane & 3) * 2;
#pragma unroll
    for (int nf = 0; nf < 4; nf++) {
        float2 bv = *(const float2*)(bias + ccol0 + nf * 8);
#pragma unroll
        for (int mi = 0; mi < 4; mi++) {
            float* c = acc[mi][nf];
            float2 v0 = make_float2(c[0] + bv.x, c[1] + bv.y);
            float2 v1 = make_float2(c[2] + bv.x, c[3] + bv.y);
            *(float2*)(C + (size_t)(crow + mi*16)     * NE + ccol0 + nf*8) = v0;
            *(float2*)(C + (size_t)(crow + mi*16 + 8) * NE + ccol0 + nf*8) = v1;
        }
    }
}

// ---------------------------------------------------------------------------
// Flash attention, fp32 SIMT (round-1 passing version, unchanged).
// ---------------------------------------------------------------------------
__global__ __launch_bounds__(256, 2)
void attn_kernel(const float* __restrict__ Q, const float* __restrict__ K,
                 const float* __restrict__ V, float* __restrict__ Y)
{
    __shared__ float Qs[64][64];
    __shared__ float Ks[64][64];
    __shared__ float Vs[64][64];

    const int tid = threadIdx.x;
    const int ty  = tid >> 4;
    const int tx  = tid & 15;
    const int qt  = (int)gridDim.x - 1 - (int)blockIdx.x;
    const int bh  = blockIdx.y;
    const int b   = bh >> 4;
    const int h   = bh & 15;
    const size_t base = (size_t)b * TSEQ * NE + (size_t)h * DKH;

#pragma unroll
    for (int it = 0; it < 4; it++) {
        int idx = tid + it * 256;
        int r   = idx >> 4;
        int blk = idx & 15;
        float4 v = *(const float4*)(Q + base + (size_t)(qt*64 + r) * NE + blk*4);
        v.x *= 0.125f; v.y *= 0.125f; v.z *= 0.125f; v.w *= 0.125f;
        ((float4*)&Qs[r][0])[blk ^ (r >> 2)] = v;
    }

    float m_r[4], l_r[4], o[4][4];
#pragma unroll
    for (int i = 0; i < 4; i++) {
        m_r[i] = -1e30f; l_r[i] = 0.f;
#pragma unroll
        for (int j = 0; j < 4; j++) o[i][j] = 0.f;
    }
    __syncthreads();

    for (int kt = 0; kt <= qt; kt++) {
#pragma unroll
        for (int it = 0; it < 4; it++) {
            int idx = tid + it * 256;
            int r   = idx >> 4;
            int blk = idx & 15;
            int sw  = blk ^ (r >> 2);
            ((float4*)&Ks[r][0])[sw] = *(const float4*)(K + base + (size_t)(kt*64 + r) * NE + blk*4);
            ((float4*)&Vs[r][0])[sw] = *(const float4*)(V + base + (size_t)(kt*64 + r) * NE + blk*4);
        }
        __syncthreads();

        float s[4][4];
#pragma unroll
        for (int i = 0; i < 4; i++)
#pragma unroll
            for (int j = 0; j < 4; j++) s[i][j] = 0.f;

#pragma unroll
        for (int d4 = 0; d4 < 16; d4++) {
            float4 a[4];
#pragma unroll
            for (int i = 0; i < 4; i++)
                a[i] = ((const float4*)&Qs[ty*4 + i][0])[d4 ^ ty];
#pragma unroll
            for (int j = 0; j < 4; j++) {
                float4 bb = ((const float4*)&Ks[tx*4 + j][0])[d4 ^ tx];
#pragma unroll
                for (int i = 0; i < 4; i++)
                    s[i][j] += a[i].x*bb.x + a[i].y*bb.y + a[i].z*bb.z + a[i].w*bb.w;
            }
        }

        if (kt == qt) {
#pragma unroll
            for (int i = 0; i < 4; i++)
#pragma unroll
                for (int j = 0; j < 4; j++)
                    if (tx*4 + j > ty*4 + i) s[i][j] = -1e30f;
        }

#pragma unroll
        for (int i = 0; i < 4; i++) {
            float mx = fmaxf(fmaxf(s[i][0], s[i][1]), fmaxf(s[i][2], s[i][3]));
#pragma unroll
            for (int off = 1; off < 16; off <<= 1)
                mx = fmaxf(mx, __shfl_xor_sync(0xffffffffu, mx, off));
            float mnew = fmaxf(m_r[i], mx);
            float corr = __expf(m_r[i] - mnew);
            float rsum = 0.f;
#pragma unroll
            for (int j = 0; j < 4; j++) { s[i][j] = __expf(s[i][j] - mnew); rsum += s[i][j]; }
#pragma unroll
            for (int off = 1; off < 16; off <<= 1)
                rsum += __shfl_xor_sync(0xffffffffu, rsum, off);
            l_r[i] = l_r[i] * corr + rsum;
            m_r[i] = mnew;
#pragma unroll
            for (int j = 0; j < 4; j++) o[i][j] *= corr;
        }

        __syncthreads();
#pragma unroll
        for (int j = 0; j < 4; j++) {
            int c = tx*4 + j;
#pragma unroll
            for (int i = 0; i < 4; i++)
                Ks[c][((ty ^ tx) << 2) + i] = s[i][j];
        }
        __syncthreads();

#pragma unroll 8
        for (int c = 0; c < 64; c++) {
            int sw = c >> 2;
            float4 a  = ((const float4*)&Ks[c][0])[ty ^ sw];
            float4 bb = ((const float4*)&Vs[c][0])[tx ^ sw];
            o[0][0] += a.x*bb.x; o[0][1] += a.x*bb.y; o[0][2] += a.x*bb.z; o[0][3] += a.x*bb.w;
            o[1][0] += a.y*bb.x; o[1][1] += a.y*bb.y; o[1][2] += a.y*bb.z; o[1][3] += a.y*bb.w;
            o[2][0] += a.z*bb.x; o[2][1] += a.z*bb.y; o[2][2] += a.z*bb.z; o[2][3] += a.z*bb.w;
            o[3][0] += a.w*bb.x; o[3][1] += a.w*bb.y; o[3][2] += a.w*bb.z; o[3][3] += a.w*bb.w;
        }
        __syncthreads();
    }

#pragma unroll
    for (int i = 0; i < 4; i++) {
        float inv = 1.f / l_r[i];
        float4 out = make_float4(o[i][0]*inv, o[i][1]*inv, o[i][2]*inv, o[i][3]*inv);
        *(float4*)(Y + base + (size_t)(qt*64 + ty*4 + i) * NE + tx*4) = out;
    }
}

// ---------------------------------------------------------------------------
extern "C" void kernel_launch(void* const* d_in, const int* in_sizes, int n_in,
                              void* d_out, int out_size)
{
    const float* x  = (const float*)d_in[0];
    const float* Wq = (const float*)d_in[1];
    const float* bq = (const float*)d_in[2];
    const float* Wk = (const float*)d_in[3];
    const float* bk = (const float*)d_in[4];
    const float* Wv = (const float*)d_in[5];
    const float* bv = (const float*)d_in[6];
    const float* Wo = (const float*)d_in[7];
    const float* bo = (const float*)d_in[8];
    float* out = (float*)d_out;

    float *Qp, *Kp, *Vp, *Yp;
    cudaGetSymbolAddress((void**)&Qp, g_Q);
    cudaGetSymbolAddress((void**)&Kp, g_K);
    cudaGetSymbolAddress((void**)&Vp, g_V);
    cudaGetSymbolAddress((void**)&Yp, g_Y);

    static bool attr_done = false;
    if (!attr_done) {
        cudaFuncSetAttribute(gemm_tc, cudaFuncAttributeMaxDynamicSharedMemorySize, SMEM_DYN);
        attr_done = true;
    }

    gemm_tc<<<dim3(8, 32, 3), 256, SMEM_DYN>>>(x, Wq, Wk, Wv, bq, bk, bv, Qp, Kp, Vp);
    attn_kernel<<<dim3(32, 32), 256>>>(Qp, Kp, Vp, Yp);
    gemm_tc<<<dim3(8, 32, 1), 256, SMEM_DYN>>>(Yp, Wo, Wo, Wo, bo, bo, bo, out, out, out);
}

// round 6
// speedup vs baseline: 2.8038x; 1.7576x over previous
#include <cuda_runtime.h>
#include <cuda_bf16.h>
#include <cstdint>
#include <math.h>

#define TSEQ 2048
#define NE   1024
#define NH   16
#define DKH  64
#define NB   2
#define MTOT (NB*TSEQ)   // 4096

// Scratch (allocation-free)
__device__ float g_Q[MTOT*NE];
__device__ float g_K[MTOT*NE];
__device__ float g_V[MTOT*NE];
__device__ float g_Y[MTOT*NE];

// ---------------------------------------------------------------------------
// Baseline-PTX tensor ops (plain sm_103 target: mma.sync + ldmatrix only)
// ---------------------------------------------------------------------------
static __device__ __forceinline__ uint32_t smem_u32(const void* p) {
    uint32_t a;
    asm("{ .reg .u64 t; cvta.to.shared.u64 t, %1; cvt.u32.u64 %0, t; }" : "=r"(a) : "l"(p));
    return a;
}
static __device__ __forceinline__ void ldsm_x4(uint32_t& r0, uint32_t& r1,
                                               uint32_t& r2, uint32_t& r3, uint32_t a) {
    asm volatile("ldmatrix.sync.aligned.m8n8.x4.shared.b16 {%0,%1,%2,%3}, [%4];"
                 : "=r"(r0), "=r"(r1), "=r"(r2), "=r"(r3) : "r"(a));
}
static __device__ __forceinline__ void ldsm_x4_t(uint32_t& r0, uint32_t& r1,
                                                 uint32_t& r2, uint32_t& r3, uint32_t a) {
    asm volatile("ldmatrix.sync.aligned.m8n8.x4.trans.shared.b16 {%0,%1,%2,%3}, [%4];"
                 : "=r"(r0), "=r"(r1), "=r"(r2), "=r"(r3) : "r"(a));
}
static __device__ __forceinline__ void mma16816(float* c, const uint32_t* a, const uint32_t* b) {
    asm volatile("mma.sync.aligned.m16n8k16.row.col.f32.bf16.bf16.f32 "
                 "{%0,%1,%2,%3}, {%4,%5,%6,%7}, {%8,%9}, {%0,%1,%2,%3};"
                 : "+f"(c[0]), "+f"(c[1]), "+f"(c[2]), "+f"(c[3])
                 : "r"(a[0]), "r"(a[1]), "r"(a[2]), "r"(a[3]), "r"(b[0]), "r"(b[1]));
}

// Split fp32 quad -> hi/lo bf16 quads, store 8B each.
static __device__ __forceinline__ void split_store(char* hi, char* lo, float4 v) {
    __nv_bfloat16 hx = __float2bfloat16_rn(v.x), hy = __float2bfloat16_rn(v.y);
    __nv_bfloat16 hz = __float2bfloat16_rn(v.z), hw = __float2bfloat16_rn(v.w);
    union { __nv_bfloat162 h[2]; uint2 u; } p;
    p.h[0].x = hx; p.h[0].y = hy; p.h[1].x = hz; p.h[1].y = hw;
    *(uint2*)hi = p.u;
    p.h[0].x = __float2bfloat16_rn(v.x - __bfloat162float(hx));
    p.h[0].y = __float2bfloat16_rn(v.y - __bfloat162float(hy));
    p.h[1].x = __float2bfloat16_rn(v.z - __bfloat162float(hz));
    p.h[1].y = __float2bfloat16_rn(v.w - __bfloat162float(hw));
    *(uint2*)lo = p.u;
}
// Split two fp32 into packed hi bf16x2 + lo bf16x2
static __device__ __forceinline__ void pack_split(float x, float y, uint32_t& h, uint32_t& l) {
    union { __nv_bfloat162 b; uint32_t u; } ph, pl;
    __nv_bfloat16 hx = __float2bfloat16_rn(x), hy = __float2bfloat16_rn(y);
    ph.b.x = hx; ph.b.y = hy;
    pl.b.x = __float2bfloat16_rn(x - __bfloat162float(hx));
    pl.b.y = __float2bfloat16_rn(y - __bfloat162float(hy));
    h = ph.u; l = pl.u;
}

#define RSTRIDE   80                 // GEMM: 32 bf16 (64B) + pad
#define TILE_B    (128 * RSTRIDE)
#define STAGE     (4 * TILE_B)
#define SMEM_DYN  (2 * STAGE)
#define NK        (NE / 32)

// ---------------------------------------------------------------------------
// GEMM: C = A * W^T + bias, split-bf16 HMMA (unchanged, passing at 261us).
// ---------------------------------------------------------------------------
__global__ __launch_bounds__(256)
void gemm_tc(const float* __restrict__ A,
             const float* __restrict__ W0, const float* __restrict__ W1, const float* __restrict__ W2,
             const float* __restrict__ b0, const float* __restrict__ b1, const float* __restrict__ b2,
             float* __restrict__ C0, float* __restrict__ C1, float* __restrict__ C2)
{
    extern __shared__ char smem[];

    const float* W; const float* bias; float* C;
    if (blockIdx.z == 0)      { W = W0; bias = b0; C = C0; }
    else if (blockIdx.z == 1) { W = W1; bias = b1; C = C1; }
    else                      { W = W2; bias = b2; C = C2; }

    const int tid  = threadIdx.x;
    const int wid  = tid >> 5;
    const int lane = tid & 31;
    const int mbase = blockIdx.y * 128;
    const int nbase = blockIdx.x * 128;
    const int warp_m = wid >> 2;
    const int warp_n = wid & 3;

    const int r0 = tid >> 3;
    const int c4 = tid & 7;

    const int la_row = warp_m * 64 + (lane & 15);
    const int la_k8  = ((lane >> 4) & 1) * 8;
    const int lw_row = warp_n * 32 + (lane & 7) + ((lane >> 4) & 1) * 8;
    const int lw_k8  = ((lane >> 3) & 1) * 8;

    const uint32_t smb = smem_u32(smem);

    float acc[4][4][4];
#pragma unroll
    for (int mi = 0; mi < 4; mi++)
#pragma unroll
        for (int nf = 0; nf < 4; nf++)
#pragma unroll
            for (int q = 0; q < 4; q++) acc[mi][nf][q] = 0.f;

    float4 ra[4], rw[4];

#pragma unroll
    for (int i = 0; i < 4; i++) {
        ra[i] = *(const float4*)(A + (size_t)(mbase + r0 + 32*i) * NE + c4 * 4);
        rw[i] = *(const float4*)(W + (size_t)(nbase + r0 + 32*i) * NE + c4 * 4);
    }
#pragma unroll
    for (int i = 0; i < 4; i++) {
        uint32_t off = (uint32_t)(r0 + 32*i) * RSTRIDE + c4 * 8;
        split_store(smem + off,            smem + TILE_B + off,   ra[i]);
        split_store(smem + 2*TILE_B + off, smem + 3*TILE_B + off, rw[i]);
    }
    __syncthreads();

    for (int kt = 0; kt < NK; kt++) {
        const int b = kt & 1;
        if (kt + 1 < NK) {
            const float* Ap = A + (size_t)mbase * NE + (kt + 1) * 32;
            const float* Wp = W + (size_t)nbase * NE + (kt + 1) * 32;
#pragma unroll
            for (int i = 0; i < 4; i++) {
                ra[i] = *(const float4*)(Ap + (size_t)(r0 + 32*i) * NE + c4 * 4);
                rw[i] = *(const float4*)(Wp + (size_t)(r0 + 32*i) * NE + c4 * 4);
            }
        }

        const uint32_t base = smb + b * STAGE;
#pragma unroll
        for (int ks = 0; ks < 2; ks++) {
            uint32_t ah[4][4], al[4][4];
#pragma unroll
            for (int mi = 0; mi < 4; mi++) {
                uint32_t aoff = (uint32_t)(la_row + mi*16) * RSTRIDE + (ks*16 + la_k8) * 2;
                ldsm_x4(ah[mi][0], ah[mi][1], ah[mi][2], ah[mi][3], base + aoff);
                ldsm_x4(al[mi][0], al[mi][1], al[mi][2], al[mi][3], base + TILE_B + aoff);
            }
            uint32_t wh[2][4], wl[2][4];
#pragma unroll
            for (int nj = 0; nj < 2; nj++) {
                uint32_t woff = (uint32_t)(lw_row + nj*16) * RSTRIDE + (ks*16 + lw_k8) * 2;
                ldsm_x4(wh[nj][0], wh[nj][1], wh[nj][2], wh[nj][3], base + 2*TILE_B + woff);
                ldsm_x4(wl[nj][0], wl[nj][1], wl[nj][2], wl[nj][3], base + 3*TILE_B + woff);
            }
#pragma unroll
            for (int mi = 0; mi < 4; mi++)
#pragma unroll
                for (int nf = 0; nf < 4; nf++) {
                    const uint32_t* bh = &wh[nf >> 1][(nf & 1) * 2];
                    const uint32_t* bl = &wl[nf >> 1][(nf & 1) * 2];
                    mma16816(acc[mi][nf], ah[mi], bh);
                    mma16816(acc[mi][nf], ah[mi], bl);
                    mma16816(acc[mi][nf], al[mi], bh);
                }
        }

        if (kt + 1 < NK) {
            char* stg = smem + ((kt + 1) & 1) * STAGE;
#pragma unroll
            for (int i = 0; i < 4; i++) {
                uint32_t off = (uint32_t)(r0 + 32*i) * RSTRIDE + c4 * 8;
                split_store(stg + off,            stg + TILE_B + off,   ra[i]);
                split_store(stg + 2*TILE_B + off, stg + 3*TILE_B + off, rw[i]);
            }
            __syncthreads();
        }
    }

    const int crow  = mbase + warp_m * 64 + (lane >> 2);
    const int ccol0 = nbase + warp_n * 32 + (lane & 3) * 2;
#pragma unroll
    for (int nf = 0; nf < 4; nf++) {
        float2 bv = *(const float2*)(bias + ccol0 + nf * 8);
#pragma unroll
        for (int mi = 0; mi < 4; mi++) {
            float* c = acc[mi][nf];
            float2 v0 = make_float2(c[0] + bv.x, c[1] + bv.y);
            float2 v1 = make_float2(c[2] + bv.x, c[3] + bv.y);
            *(float2*)(C + (size_t)(crow + mi*16)     * NE + ccol0 + nf*8) = v0;
            *(float2*)(C + (size_t)(crow + mi*16 + 8) * NE + ccol0 + nf*8) = v1;
        }
    }
}

// ---------------------------------------------------------------------------
// Tensorized flash attention, split-bf16 mma.sync.
// CTA: 64 q-rows, 4 warps (warp = 16 q-rows), key tiles of 64, d=64.
// Row stride 144 B = 64 bf16 (128B data) + 16B pad -> conflict-free ldmatrix.
// Loader: 128 threads, 16 threads/row -> 8 rows/pass, 8 passes for 64 rows.
// ---------------------------------------------------------------------------
#define ARSTRIDE 144
#define ATILE    (64 * ARSTRIDE)       // 9216 per bf16 tile
#define ASMEM    (4 * ATILE)           // 36864

__global__ __launch_bounds__(128, 3)
void attn_tc(const float* __restrict__ Q, const float* __restrict__ K,
             const float* __restrict__ V, float* __restrict__ Y)
{
    extern __shared__ char smem[];
    const int tid  = threadIdx.x;
    const int wid  = tid >> 5;
    const int lane = tid & 31;
    const int qt   = (int)gridDim.x - 1 - (int)blockIdx.x;   // heavy first
    const int bh   = blockIdx.y;
    const int b    = bh >> 4;
    const int h    = bh & 15;
    const size_t base = (size_t)b * TSEQ * NE + (size_t)h * DKH;
    const int qb   = qt * 64;
    const uint32_t smb = smem_u32(smem);

    // Loader mapping: 16 threads per row, 8 rows per pass.
    const int lrow = tid >> 4;          // 0..7
    const int lc4  = tid & 15;          // 0..15 -> floats lc4*4..+3

    // ---- Load + split Q tile into smem (Qh at 0, Ql at ATILE), prescaled ----
#pragma unroll
    for (int half = 0; half < 2; half++) {
        float4 v[4];
#pragma unroll
        for (int i = 0; i < 4; i++) {
            int row = lrow + 8 * (half * 4 + i);
            v[i] = *(const float4*)(Q + base + (size_t)(qb + row) * NE + lc4 * 4);
            v[i].x *= 0.125f; v[i].y *= 0.125f; v[i].z *= 0.125f; v[i].w *= 0.125f;
        }
#pragma unroll
        for (int i = 0; i < 4; i++) {
            int row = lrow + 8 * (half * 4 + i);
            uint32_t off = (uint32_t)row * ARSTRIDE + lc4 * 8;
            split_store(smem + off, smem + ATILE + off, v[i]);
        }
    }
    __syncthreads();

    // ---- Q fragments to registers (held for whole kernel) ----
    const int la_row = wid * 16 + (lane & 15);
    const int la_k8  = ((lane >> 4) & 1) * 8;
    uint32_t qh[4][4], ql[4][4];
#pragma unroll
    for (int ks = 0; ks < 4; ks++) {
        uint32_t aoff = (uint32_t)la_row * ARSTRIDE + (ks * 16 + la_k8) * 2;
        ldsm_x4(qh[ks][0], qh[ks][1], qh[ks][2], qh[ks][3], smb + aoff);
        ldsm_x4(ql[ks][0], ql[ks][1], ql[ks][2], ql[ks][3], smb + ATILE + aoff);
    }
    __syncthreads();   // Q staging area about to be overwritten by K

    // K b-frag lane offsets (non-trans: rows=key, cols=d)
    const int lw_row = (lane & 7) + ((lane >> 4) & 1) * 8;
    const int lw_k8  = ((lane >> 3) & 1) * 8;
    // V b-frag lane offsets (trans: rows=key, cols=d -> frag of V^T)
    const int vt_row = (lane & 7) + ((lane >> 3) & 1) * 8;
    const int vt_cb  = ((lane >> 4) & 1) * 16;      // byte offset within d16

    float m_r[2] = {-1e30f, -1e30f}, l_r[2] = {0.f, 0.f};
    float o[8][4];
#pragma unroll
    for (int nf = 0; nf < 8; nf++)
#pragma unroll
        for (int q = 0; q < 4; q++) o[nf][q] = 0.f;

    const int nkt = qt + 1;
    for (int kt = 0; kt < nkt; kt++) {
        const int ktb = kt * 64;
        // ---- load K,V tile, split into smem (all 64 rows) ----
#pragma unroll
        for (int half = 0; half < 2; half++) {
            float4 lk[4], lv[4];
#pragma unroll
            for (int i = 0; i < 4; i++) {
                int row = lrow + 8 * (half * 4 + i);
                lk[i] = *(const float4*)(K + base + (size_t)(ktb + row) * NE + lc4 * 4);
                lv[i] = *(const float4*)(V + base + (size_t)(ktb + row) * NE + lc4 * 4);
            }
#pragma unroll
            for (int i = 0; i < 4; i++) {
                int row = lrow + 8 * (half * 4 + i);
                uint32_t off = (uint32_t)row * ARSTRIDE + lc4 * 8;
                split_store(smem + off,             smem + ATILE + off,     lk[i]);
                split_store(smem + 2*ATILE + off,   smem + 3*ATILE + off,   lv[i]);
            }
        }
        __syncthreads();

        // ---- S = Q K^T (split-bf16, 3 mma terms) ----
        float s[8][4];
#pragma unroll
        for (int nf = 0; nf < 8; nf++)
#pragma unroll
            for (int q = 0; q < 4; q++) s[nf][q] = 0.f;

#pragma unroll
        for (int ks = 0; ks < 4; ks++) {
            uint32_t kh[4][4], kl[4][4];
#pragma unroll
            for (int nj = 0; nj < 4; nj++) {
                uint32_t woff = (uint32_t)(nj * 16 + lw_row) * ARSTRIDE + (ks * 16 + lw_k8) * 2;
                ldsm_x4(kh[nj][0], kh[nj][1], kh[nj][2], kh[nj][3], smb + woff);
                ldsm_x4(kl[nj][0], kl[nj][1], kl[nj][2], kl[nj][3], smb + ATILE + woff);
            }
#pragma unroll
            for (int nf = 0; nf < 8; nf++) {
                const uint32_t* bh = &kh[nf >> 1][(nf & 1) * 2];
                const uint32_t* bl = &kl[nf >> 1][(nf & 1) * 2];
                mma16816(s[nf], qh[ks], bh);
                mma16816(s[nf], qh[ks], bl);
                mma16816(s[nf], ql[ks], bh);
            }
        }

        // ---- causal mask (only diagonal tile) ----
        if (kt == nkt - 1) {
            const int rl0 = wid * 16 + (lane >> 2);
#pragma unroll
            for (int nf = 0; nf < 8; nf++) {
                int cl = nf * 8 + (lane & 3) * 2;
                if (cl     > rl0)     s[nf][0] = -1e30f;
                if (cl + 1 > rl0)     s[nf][1] = -1e30f;
                if (cl     > rl0 + 8) s[nf][2] = -1e30f;
                if (cl + 1 > rl0 + 8) s[nf][3] = -1e30f;
            }
        }

        // ---- online softmax (rows r0=lane>>2, r1=r0+8; cols across lane&3) ----
        float corr[2];
#pragma unroll
        for (int r = 0; r < 2; r++) {
            float mx = -1e30f;
#pragma unroll
            for (int nf = 0; nf < 8; nf++)
                mx = fmaxf(mx, fmaxf(s[nf][2*r], s[nf][2*r + 1]));
            mx = fmaxf(mx, __shfl_xor_sync(0xffffffffu, mx, 1));
            mx = fmaxf(mx, __shfl_xor_sync(0xffffffffu, mx, 2));
            float mnew = fmaxf(m_r[r], mx);
            corr[r] = __expf(m_r[r] - mnew);
            float ps = 0.f;
#pragma unroll
            for (int nf = 0; nf < 8; nf++) {
                float p0 = __expf(s[nf][2*r]     - mnew);
                float p1 = __expf(s[nf][2*r + 1] - mnew);
                s[nf][2*r] = p0; s[nf][2*r + 1] = p1;
                ps += p0 + p1;
            }
            ps += __shfl_xor_sync(0xffffffffu, ps, 1);
            ps += __shfl_xor_sync(0xffffffffu, ps, 2);
            l_r[r] = l_r[r] * corr[r] + ps;
            m_r[r] = mnew;
        }
#pragma unroll
        for (int nf = 0; nf < 8; nf++) {
            o[nf][0] *= corr[0]; o[nf][1] *= corr[0];
            o[nf][2] *= corr[1]; o[nf][3] *= corr[1];
        }

        // ---- O += P V (P from regs, split; V via ldmatrix.trans, split) ----
#pragma unroll
        for (int ks2 = 0; ks2 < 4; ks2++) {
            uint32_t pa_h[4], pa_l[4];
            pack_split(s[2*ks2][0],     s[2*ks2][1],     pa_h[0], pa_l[0]);
            pack_split(s[2*ks2][2],     s[2*ks2][3],     pa_h[1], pa_l[1]);
            pack_split(s[2*ks2 + 1][0], s[2*ks2 + 1][1], pa_h[2], pa_l[2]);
            pack_split(s[2*ks2 + 1][2], s[2*ks2 + 1][3], pa_h[3], pa_l[3]);

            uint32_t vh[4][4], vl[4][4];
#pragma unroll
            for (int df = 0; df < 4; df++) {
                uint32_t voff = (uint32_t)(ks2 * 16 + vt_row) * ARSTRIDE + df * 32 + vt_cb;
                ldsm_x4_t(vh[df][0], vh[df][1], vh[df][2], vh[df][3], smb + 2*ATILE + voff);
                ldsm_x4_t(vl[df][0], vl[df][1], vl[df][2], vl[df][3], smb + 3*ATILE + voff);
            }
#pragma unroll
            for (int nf = 0; nf < 8; nf++) {
                const uint32_t* bh = &vh[nf >> 1][(nf & 1) * 2];
                const uint32_t* bl = &vl[nf >> 1][(nf & 1) * 2];
                mma16816(o[nf], pa_h, bh);
                mma16816(o[nf], pa_l, bh);
                mma16816(o[nf], pa_h, bl);
            }
        }
        __syncthreads();
    }

    // ---- normalize + store ----
    const float inv0 = 1.f / l_r[0];
    const float inv1 = 1.f / l_r[1];
    const int grow = qb + wid * 16 + (lane >> 2);
    const int d0 = (lane & 3) * 2;
#pragma unroll
    for (int nf = 0; nf < 8; nf++) {
        *(float2*)(Y + base + (size_t)grow * NE + nf * 8 + d0) =
            make_float2(o[nf][0] * inv0, o[nf][1] * inv0);
        *(float2*)(Y + base + (size_t)(grow + 8) * NE + nf * 8 + d0) =
            make_float2(o[nf][2] * inv1, o[nf][3] * inv1);
    }
}

// ---------------------------------------------------------------------------
extern "C" void kernel_launch(void* const* d_in, const int* in_sizes, int n_in,
                              void* d_out, int out_size)
{
    const float* x  = (const float*)d_in[0];
    const float* Wq = (const float*)d_in[1];
    const float* bq = (const float*)d_in[2];
    const float* Wk = (const float*)d_in[3];
    const float* bk = (const float*)d_in[4];
    const float* Wv = (const float*)d_in[5];
    const float* bv = (const float*)d_in[6];
    const float* Wo = (const float*)d_in[7];
    const float* bo = (const float*)d_in[8];
    float* out = (float*)d_out;

    float *Qp, *Kp, *Vp, *Yp;
    cudaGetSymbolAddress((void**)&Qp, g_Q);
    cudaGetSymbolAddress((void**)&Kp, g_K);
    cudaGetSymbolAddress((void**)&Vp, g_V);
    cudaGetSymbolAddress((void**)&Yp, g_Y);

    static bool attr_done = false;
    if (!attr_done) {
        cudaFuncSetAttribute(gemm_tc, cudaFuncAttributeMaxDynamicSharedMemorySize, SMEM_DYN);
        attr_done = true;
    }

    gemm_tc<<<dim3(8, 32, 3), 256, SMEM_DYN>>>(x, Wq, Wk, Wv, bq, bk, bv, Qp, Kp, Vp);
    attn_tc<<<dim3(32, 32), 128, ASMEM>>>(Qp, Kp, Vp, Yp);
    gemm_tc<<<dim3(8, 32, 1), 256, SMEM_DYN>>>(Yp, Wo, Wo, Wo, bo, bo, bo, out, out, out);
}